// round 1
// baseline (speedup 1.0000x reference)
#include <cuda_runtime.h>

#define TT 2048
#define BB 64
#define HH 128
#define GG 384
#define MTOT (BB * TT)   // 131072

// Scratch (device globals: no runtime allocation allowed)
__device__ float g_gx[(size_t)MTOT * GG];    // [B,T,3H] pre-activations, ~201MB
__device__ float g_bufA[(size_t)MTOT * HH];  // layer output ping, ~67MB
__device__ float g_bufB[(size_t)MTOT * HH];  // layer output pong, ~67MB

// ---------- packed f32x2 helpers (sm_100+ PTX) ----------
__device__ __forceinline__ unsigned long long pk2(float x, float y) {
    unsigned long long r;
    asm("mov.b64 %0, {%1, %2};" : "=l"(r) : "f"(x), "f"(y));
    return r;
}
__device__ __forceinline__ void upk2(unsigned long long v, float& x, float& y) {
    asm("mov.b64 {%0, %1}, %2;" : "=f"(x), "=f"(y) : "l"(v));
}
__device__ __forceinline__ unsigned long long ffma2(unsigned long long a,
                                                    unsigned long long b,
                                                    unsigned long long c) {
    unsigned long long d;
    asm("fma.rn.f32x2 %0, %1, %2, %3;" : "=l"(d) : "l"(a), "l"(b), "l"(c));
    return d;
}
__device__ __forceinline__ float sigm(float x) {
    return 1.0f / (1.0f + __expf(-x));
}

// ============================================================================
// Persistent GRU scan: one CTA per batch row, full T loop on-chip.
//   gates pre-x:  gx[b][t][c] = (x @ kernel + bias_in)[c]   (precomputed)
//   per step:     acc[c] = bias_rec[c] + sum_k h[k] * rec[k][c]
//                 z = sig(gx_z + acc_z); r = sig(gx_r + acc_r)
//                 cand = tanh(gx_h + r * acc_h)
//                 h = z*h + (1-z)*cand
// Weights: each thread owns one gate column in 64 packed-f32x2 registers.
// h: shared, read as 16B packed pairs (directly valid f32x2 operands).
// ============================================================================
__global__ void __launch_bounds__(GG, 1) gru_scan(
    const float* __restrict__ gx,    // [B, T, 384]
    const float* __restrict__ rec,   // [128, 384]
    const float* __restrict__ brec,  // [384]
    float* __restrict__ out)         // [B, T, 128]
{
    __shared__ __align__(16) float h[HH];
    __shared__ float s[GG];
    __shared__ float sgxh[HH];

    const int b = blockIdx.x;
    const int c = threadIdx.x;  // gate column 0..383

    // Load this thread's weight column as 64 packed pairs (k-pairs).
    unsigned long long w2[64];
#pragma unroll
    for (int p = 0; p < 64; ++p)
        w2[p] = pk2(rec[(2 * p) * GG + c], rec[(2 * p + 1) * GG + c]);
    const float brc = brec[c];

    if (c < HH) h[c] = 0.0f;

    const float* gxp = gx + (size_t)b * TT * GG + c;
    float* outp = out + (size_t)b * TT * HH;

    // software-pipelined gx prefetch (distance 2)
    float g0 = gxp[0];
    float g1 = gxp[GG];
    __syncthreads();

    for (int t = 0; t < TT; ++t) {
        float gxv = g0;
        g0 = g1;
        int tp = t + 2;
        if (tp > TT - 1) tp = TT - 1;
        g1 = gxp[(size_t)tp * GG];

        // GEMV: acc = brec[c] + sum_k h[k]*rec[k][c], packed f32x2
        unsigned long long acc = pk2(brc, 0.0f);
        const ulonglong2* h2 = (const ulonglong2*)h;
#pragma unroll
        for (int j = 0; j < 32; ++j) {
            ulonglong2 hv = h2[j];
            acc = ffma2(hv.x, w2[2 * j], acc);
            acc = ffma2(hv.y, w2[2 * j + 1], acc);
        }
        float ax, ay;
        upk2(acc, ax, ay);
        float a = ax + ay;

        if (c < 2 * HH) {
            s[c] = a + gxv;          // z, r gates: x-part folds in additively
        } else {
            s[c] = a;                // h gate: keep h-part separate (r * hh)
            sgxh[c - 2 * HH] = gxv;
        }
        __syncthreads();

        if (c < HH) {
            float z = sigm(s[c]);
            float r = sigm(s[c + HH]);
            float pre = sgxh[c] + r * s[c + 2 * HH];
            float cand = 2.0f * sigm(2.0f * pre) - 1.0f;  // tanh, saturation-safe
            float hn = z * h[c] + (1.0f - z) * cand;
            h[c] = hn;
            outp[(size_t)t * HH + c] = hn;
        }
        __syncthreads();
    }
}

// ============================================================================
// Tiled fp32 GEMM + bias (+ optional sigmoid): C[M,N] = A[M,128] @ B[128,N]
// BM=64, BN=64, K=128 single-shot. 256 threads, 4x4 micro-tile per thread.
// Dynamic smem: 64KB (A tile 32KB + B tile 32KB).
// ============================================================================
__global__ void __launch_bounds__(256) gemm_bias(
    const float* __restrict__ A, const float* __restrict__ Bm,
    const float* __restrict__ bias, float* __restrict__ C,
    int N, int do_sig)
{
    extern __shared__ float smem[];
    float* As = smem;            // [64][128]
    float* Bs = smem + 64 * 128; // [128][64]

    const int tid = threadIdx.x;
    const int m0 = blockIdx.x * 64;
    const int n0 = blockIdx.y * 64;

    // A tile: lda == 128 always, so the tile is one contiguous 64x128 block.
    const float4* A4 = (const float4*)(A + (size_t)m0 * 128);
    float4* As4 = (float4*)As;
#pragma unroll
    for (int i = 0; i < 8; ++i) {
        int idx = i * 256 + tid;  // 0..2047 float4s
        As4[idx] = A4[idx];
    }

    const int N4 = N >> 2;
    const float4* B4 = (const float4*)Bm;
    float4* Bs4 = (float4*)Bs;
#pragma unroll
    for (int i = 0; i < 8; ++i) {
        int idx = i * 256 + tid;  // 0..2047
        int k = idx >> 4;
        int c4 = idx & 15;
        Bs4[idx] = B4[(size_t)k * N4 + (n0 >> 2) + c4];
    }
    __syncthreads();

    const int r0 = (tid >> 4) * 4;
    const int c0 = (tid & 15) * 4;

    float acc[4][4];
#pragma unroll
    for (int i = 0; i < 4; ++i)
#pragma unroll
        for (int j = 0; j < 4; ++j) acc[i][j] = 0.0f;

#pragma unroll 4
    for (int k = 0; k < 128; ++k) {
        float4 bv = Bs4[k * 16 + (c0 >> 2)];
        float a0 = As[(r0 + 0) * 128 + k];
        float a1 = As[(r0 + 1) * 128 + k];
        float a2 = As[(r0 + 2) * 128 + k];
        float a3 = As[(r0 + 3) * 128 + k];
        acc[0][0] += a0 * bv.x; acc[0][1] += a0 * bv.y; acc[0][2] += a0 * bv.z; acc[0][3] += a0 * bv.w;
        acc[1][0] += a1 * bv.x; acc[1][1] += a1 * bv.y; acc[1][2] += a1 * bv.z; acc[1][3] += a1 * bv.w;
        acc[2][0] += a2 * bv.x; acc[2][1] += a2 * bv.y; acc[2][2] += a2 * bv.z; acc[2][3] += a2 * bv.w;
        acc[3][0] += a3 * bv.x; acc[3][1] += a3 * bv.y; acc[3][2] += a3 * bv.z; acc[3][3] += a3 * bv.w;
    }

    const float b0 = bias[n0 + c0 + 0];
    const float b1 = bias[n0 + c0 + 1];
    const float b2 = bias[n0 + c0 + 2];
    const float b3 = bias[n0 + c0 + 3];
#pragma unroll
    for (int i = 0; i < 4; ++i) {
        float4 v;
        v.x = acc[i][0] + b0;
        v.y = acc[i][1] + b1;
        v.z = acc[i][2] + b2;
        v.w = acc[i][3] + b3;
        if (do_sig) {
            v.x = sigm(v.x); v.y = sigm(v.y); v.z = sigm(v.z); v.w = sigm(v.w);
        }
        *(float4*)(C + (size_t)(m0 + r0 + i) * N + n0 + c0) = v;
    }
}

// ============================================================================
extern "C" void kernel_launch(void* const* d_in, const int* in_sizes, int n_in,
                              void* d_out, int out_size)
{
    const float* X    = (const float*)d_in[0];  // [64,2048,128]
    const float* Wk   = (const float*)d_in[1];  // [128,384]
    const float* Wr   = (const float*)d_in[2];  // [128,384]
    const float* bin  = (const float*)d_in[3];  // [384]
    const float* brec = (const float*)d_in[4];  // [384]
    const float* Wo   = (const float*)d_in[5];  // [128,128]
    const float* bo   = (const float*)d_in[6];  // [128]
    float* out = (float*)d_out;                 // [64,2048,128]

    float *gx, *bufA, *bufB;
    cudaGetSymbolAddress((void**)&gx,   g_gx);
    cudaGetSymbolAddress((void**)&bufA, g_bufA);
    cudaGetSymbolAddress((void**)&bufB, g_bufB);

    cudaFuncSetAttribute(gemm_bias, cudaFuncAttributeMaxDynamicSharedMemorySize,
                         64 * 1024);

    dim3 gg(MTOT / 64, GG / 64);  // 2048 x 6
    dim3 go(MTOT / 64, HH / 64);  // 2048 x 2

    // Layer 0
    gemm_bias<<<gg, 256, 64 * 1024>>>(X, Wk, bin, gx, GG, 0);
    gru_scan<<<BB, GG>>>(gx, Wr, brec, bufA);
    // Layer 1 (weights shared)
    gemm_bias<<<gg, 256, 64 * 1024>>>(bufA, Wk, bin, gx, GG, 0);
    gru_scan<<<BB, GG>>>(gx, Wr, brec, bufB);
    // Layer 2
    gemm_bias<<<gg, 256, 64 * 1024>>>(bufB, Wk, bin, gx, GG, 0);
    gru_scan<<<BB, GG>>>(gx, Wr, brec, bufA);
    // Output projection + sigmoid
    gemm_bias<<<go, 256, 64 * 1024>>>(bufA, Wo, bo, out, HH, 1);
}

// round 2
// speedup vs baseline: 1.0979x; 1.0979x over previous
#include <cuda_runtime.h>

#define TT 2048
#define BB 64
#define HH 128
#define GG 384
#define MTOT (BB * TT)   // 131072

// Scratch (device globals: no runtime allocation allowed)
__device__ float g_gx[(size_t)MTOT * GG];    // [B,T,3H] pre-activations
__device__ float g_bufA[(size_t)MTOT * HH];  // layer output ping
__device__ float g_bufB[(size_t)MTOT * HH];  // layer output pong

// ---------- packed f32x2 helpers (sm_100+ PTX) ----------
__device__ __forceinline__ unsigned long long pk2(float x, float y) {
    unsigned long long r;
    asm("mov.b64 %0, {%1, %2};" : "=l"(r) : "f"(x), "f"(y));
    return r;
}
__device__ __forceinline__ void upk2(unsigned long long v, float& x, float& y) {
    asm("mov.b64 {%0, %1}, %2;" : "=f"(x), "=f"(y) : "l"(v));
}
__device__ __forceinline__ unsigned long long ffma2(unsigned long long a,
                                                    unsigned long long b,
                                                    unsigned long long c) {
    unsigned long long d;
    asm("fma.rn.f32x2 %0, %1, %2, %3;" : "=l"(d) : "l"(a), "l"(b), "l"(c));
    return d;
}
__device__ __forceinline__ float sigm(float x) {
    return 1.0f / (1.0f + __expf(-x));
}

// ============================================================================
// Persistent GRU scan: one CTA per batch row, full T loop on-chip.
// Weights: each thread owns one gate column in 64 packed-f32x2 registers.
// h: shared (broadcast LDS.128 pairs) + register copy in gate threads.
// GEMV accumulation split into 2 independent chains (RAW chain 256->128 cyc).
// ============================================================================
__global__ void __launch_bounds__(GG, 1) gru_scan(
    const float* __restrict__ gx,    // [B, T, 384]
    const float* __restrict__ rec,   // [128, 384]
    const float* __restrict__ brec,  // [384]
    float* __restrict__ out)         // [B, T, 128]
{
    __shared__ __align__(16) float h[HH];
    __shared__ float s[GG];
    __shared__ float sgxh[HH];

    const int b = blockIdx.x;
    const int c = threadIdx.x;  // gate column 0..383

    // This thread's weight column as 64 packed k-pairs.
    unsigned long long w2[64];
#pragma unroll
    for (int p = 0; p < 64; ++p)
        w2[p] = pk2(rec[(2 * p) * GG + c], rec[(2 * p + 1) * GG + c]);
    const float brc = brec[c];

    float hreg = 0.0f;          // gate threads: private copy of h[c]
    if (c < HH) h[c] = 0.0f;

    const float* gxp = gx + (size_t)b * TT * GG + c;
    float* outp = out + (size_t)b * TT * HH;

    // software-pipelined gx prefetch (distance 2)
    float g0 = gxp[0];
    float g1 = gxp[GG];
    __syncthreads();

    for (int t = 0; t < TT; ++t) {
        float gxv = g0;
        g0 = g1;
        int tp = t + 2;
        tp = tp < TT ? tp : TT - 1;
        g1 = gxp[(size_t)tp * GG];

        // GEMV: acc = brec[c] + sum_k h[k]*rec[k][c], two independent chains
        unsigned long long acc0 = pk2(brc, 0.0f);
        unsigned long long acc1 = 0ull;
        const ulonglong2* h2 = (const ulonglong2*)h;
#pragma unroll
        for (int j = 0; j < 32; ++j) {
            ulonglong2 hv = h2[j];
            acc0 = ffma2(hv.x, w2[2 * j], acc0);
            acc1 = ffma2(hv.y, w2[2 * j + 1], acc1);
        }
        float a0x, a0y, a1x, a1y;
        upk2(acc0, a0x, a0y);
        upk2(acc1, a1x, a1y);
        float a = (a0x + a1x) + (a0y + a1y);

        if (c < 2 * HH) {
            s[c] = a + gxv;          // z, r gates: x-part folds in additively
        } else {
            s[c] = a;                // h gate: keep h-part separate (r * hh)
            sgxh[c - 2 * HH] = gxv;
        }
        __syncthreads();

        if (c < HH) {
            float z = sigm(s[c]);
            float r = sigm(s[c + HH]);
            float pre = sgxh[c] + r * s[c + 2 * HH];
            float cand = 2.0f * sigm(2.0f * pre) - 1.0f;  // tanh
            float hn = fmaf(z, hreg - cand, cand);        // z*h + (1-z)*cand
            hreg = hn;
            h[c] = hn;
            outp[(size_t)t * HH + c] = hn;
        }
        __syncthreads();
    }
}

// ============================================================================
// fp32 GEMM + bias (+ optional sigmoid) with packed f32x2 FMA.
// C[M,N] = A[M,128] @ B[128,N].  BM=64, BN=128, K=128 single-shot.
// 256 threads, 4x8 micro-tile (cols split as two 16B groups 64 apart ->
// conflict-free ulonglong2 shared reads). Dyn smem 96KB, 2 CTAs/SM.
// ============================================================================
__global__ void __launch_bounds__(256, 2) gemm_bias(
    const float* __restrict__ A, const float* __restrict__ Bm,
    const float* __restrict__ bias, float* __restrict__ C,
    int N, int do_sig)
{
    extern __shared__ float smem[];
    float* As = smem;            // [64][128] row-major
    float* Bs = smem + 64 * 128; // [128][128] k-major rows

    const int tid = threadIdx.x;
    const int m0 = blockIdx.x * 64;
    const int n0 = blockIdx.y * 128;

    // A tile: contiguous 64x128 block (lda==128 always).
    const float4* A4 = (const float4*)(A + (size_t)m0 * 128);
    float4* As4 = (float4*)As;
#pragma unroll
    for (int i = 0; i < 8; ++i) {
        int idx = i * 256 + tid;   // 0..2047
        As4[idx] = A4[idx];
    }
    // B tile: 128 rows x 128 cols
    const int N4 = N >> 2;
    const float4* B4 = (const float4*)Bm;
    float4* Bs4 = (float4*)Bs;
#pragma unroll
    for (int i = 0; i < 16; ++i) {
        int idx = i * 256 + tid;   // 0..4095
        int k = idx >> 5;
        int c4 = idx & 31;
        Bs4[idx] = B4[(size_t)k * N4 + (n0 >> 2) + c4];
    }
    __syncthreads();

    const int rg = tid >> 4;   // 0..15 -> rows rg*4 .. rg*4+3
    const int cg = tid & 15;   // cols cg*4..+3  and  64+cg*4..+3

    unsigned long long acc[2][4][2];
#pragma unroll
    for (int hf = 0; hf < 2; ++hf)
#pragma unroll
        for (int i = 0; i < 4; ++i) {
            acc[hf][i][0] = 0ull;
            acc[hf][i][1] = 0ull;
        }

    const ulonglong2* BsU = (const ulonglong2*)Bs;

#pragma unroll 8
    for (int k = 0; k < 128; ++k) {
        ulonglong2 bv0 = BsU[k * 32 + cg];        // cols 4cg..4cg+3
        ulonglong2 bv1 = BsU[k * 32 + 16 + cg];   // cols 64+4cg..+3
        float a0 = As[(rg * 4 + 0) * 128 + k];
        float a1 = As[(rg * 4 + 1) * 128 + k];
        float a2 = As[(rg * 4 + 2) * 128 + k];
        float a3 = As[(rg * 4 + 3) * 128 + k];
        unsigned long long aa0 = pk2(a0, a0);
        unsigned long long aa1 = pk2(a1, a1);
        unsigned long long aa2 = pk2(a2, a2);
        unsigned long long aa3 = pk2(a3, a3);

        acc[0][0][0] = ffma2(aa0, bv0.x, acc[0][0][0]);
        acc[0][0][1] = ffma2(aa0, bv0.y, acc[0][0][1]);
        acc[0][1][0] = ffma2(aa1, bv0.x, acc[0][1][0]);
        acc[0][1][1] = ffma2(aa1, bv0.y, acc[0][1][1]);
        acc[0][2][0] = ffma2(aa2, bv0.x, acc[0][2][0]);
        acc[0][2][1] = ffma2(aa2, bv0.y, acc[0][2][1]);
        acc[0][3][0] = ffma2(aa3, bv0.x, acc[0][3][0]);
        acc[0][3][1] = ffma2(aa3, bv0.y, acc[0][3][1]);
        acc[1][0][0] = ffma2(aa0, bv1.x, acc[1][0][0]);
        acc[1][0][1] = ffma2(aa0, bv1.y, acc[1][0][1]);
        acc[1][1][0] = ffma2(aa1, bv1.x, acc[1][1][0]);
        acc[1][1][1] = ffma2(aa1, bv1.y, acc[1][1][1]);
        acc[1][2][0] = ffma2(aa2, bv1.x, acc[1][2][0]);
        acc[1][2][1] = ffma2(aa2, bv1.y, acc[1][2][1]);
        acc[1][3][0] = ffma2(aa3, bv1.x, acc[1][3][0]);
        acc[1][3][1] = ffma2(aa3, bv1.y, acc[1][3][1]);
    }

#pragma unroll
    for (int hf = 0; hf < 2; ++hf) {
        int col = n0 + hf * 64 + cg * 4;
        float4 bb = *(const float4*)(bias + col);
#pragma unroll
        for (int i = 0; i < 4; ++i) {
            float4 v;
            upk2(acc[hf][i][0], v.x, v.y);
            upk2(acc[hf][i][1], v.z, v.w);
            v.x += bb.x; v.y += bb.y; v.z += bb.z; v.w += bb.w;
            if (do_sig) {
                v.x = sigm(v.x); v.y = sigm(v.y);
                v.z = sigm(v.z); v.w = sigm(v.w);
            }
            *(float4*)(C + (size_t)(m0 + rg * 4 + i) * N + col) = v;
        }
    }
}

// ============================================================================
extern "C" void kernel_launch(void* const* d_in, const int* in_sizes, int n_in,
                              void* d_out, int out_size)
{
    const float* X    = (const float*)d_in[0];  // [64,2048,128]
    const float* Wk   = (const float*)d_in[1];  // [128,384]
    const float* Wr   = (const float*)d_in[2];  // [128,384]
    const float* bin  = (const float*)d_in[3];  // [384]
    const float* brec = (const float*)d_in[4];  // [384]
    const float* Wo   = (const float*)d_in[5];  // [128,128]
    const float* bo   = (const float*)d_in[6];  // [128]
    float* out = (float*)d_out;                 // [64,2048,128]

    float *gx, *bufA, *bufB;
    cudaGetSymbolAddress((void**)&gx,   g_gx);
    cudaGetSymbolAddress((void**)&bufA, g_bufA);
    cudaGetSymbolAddress((void**)&bufB, g_bufB);

    const int smem = (64 * 128 + 128 * 128) * 4;  // 96KB
    cudaFuncSetAttribute(gemm_bias, cudaFuncAttributeMaxDynamicSharedMemorySize,
                         smem);

    dim3 gg(MTOT / 64, GG / 128);  // 2048 x 3
    dim3 go(MTOT / 64, HH / 128);  // 2048 x 1

    // Layer 0
    gemm_bias<<<gg, 256, smem>>>(X, Wk, bin, gx, GG, 0);
    gru_scan<<<BB, GG>>>(gx, Wr, brec, bufA);
    // Layer 1 (weights shared)
    gemm_bias<<<gg, 256, smem>>>(bufA, Wk, bin, gx, GG, 0);
    gru_scan<<<BB, GG>>>(gx, Wr, brec, bufB);
    // Layer 2
    gemm_bias<<<gg, 256, smem>>>(bufB, Wk, bin, gx, GG, 0);
    gru_scan<<<BB, GG>>>(gx, Wr, brec, bufA);
    // Output projection + sigmoid
    gemm_bias<<<go, 256, smem>>>(bufA, Wo, bo, out, HH, 1);
}

// round 3
// speedup vs baseline: 1.8864x; 1.7183x over previous
#include <cuda_runtime.h>

#define TT 2048
#define BB 64
#define HH 128
#define GG 384
#define MTOT (BB * TT)   // 131072
#define NC 8             // pipeline chunks
#define TCH (TT / NC)    // 256 steps per chunk
#define SMEMG ((64 * 128 + 128 * 128) * 4)

// Scratch (device globals: no runtime allocation allowed)
__device__ float g_gx[(size_t)3 * MTOT * GG];   // per-layer pre-activations
__device__ float g_buf[(size_t)3 * MTOT * HH];  // per-layer outputs
__device__ float g_h[3 * BB * HH];              // chunk-boundary hidden state

// ---------- packed f32x2 helpers (sm_100+ PTX) ----------
__device__ __forceinline__ unsigned long long pk2(float x, float y) {
    unsigned long long r;
    asm("mov.b64 %0, {%1, %2};" : "=l"(r) : "f"(x), "f"(y));
    return r;
}
__device__ __forceinline__ void upk2(unsigned long long v, float& x, float& y) {
    asm("mov.b64 {%0, %1}, %2;" : "=f"(x), "=f"(y) : "l"(v));
}
__device__ __forceinline__ unsigned long long ffma2(unsigned long long a,
                                                    unsigned long long b,
                                                    unsigned long long c) {
    unsigned long long d;
    asm("fma.rn.f32x2 %0, %1, %2, %3;" : "=l"(d) : "l"(a), "l"(b), "l"(c));
    return d;
}
__device__ __forceinline__ float sigm(float x) {
    return 1.0f / (1.0f + __expf(-x));
}

// ============================================================================
// Chunked persistent GRU scan: one CTA per batch row, steps [t0, t0+TCH).
// Hidden state carried across chunks via hstate[b][128].
// ============================================================================
__global__ void __launch_bounds__(GG, 1) gru_scan(
    const float* __restrict__ gx,    // [B, T, 384]
    const float* __restrict__ rec,   // [128, 384]
    const float* __restrict__ brec,  // [384]
    float* __restrict__ out,         // [B, T, 128]
    float* __restrict__ hstate,      // [B, 128]
    int t0)
{
    __shared__ __align__(16) float h[HH];
    __shared__ float s[GG];
    __shared__ float sgxh[HH];

    const int b = blockIdx.x;
    const int c = threadIdx.x;  // gate column 0..383

    unsigned long long w2[64];
#pragma unroll
    for (int p = 0; p < 64; ++p)
        w2[p] = pk2(rec[(2 * p) * GG + c], rec[(2 * p + 1) * GG + c]);
    const float brc = brec[c];

    float hreg = 0.0f;
    if (c < HH) {
        hreg = (t0 == 0) ? 0.0f : hstate[b * HH + c];
        h[c] = hreg;
    }

    const float* gxp = gx + (size_t)b * TT * GG + c;
    float* outp = out + (size_t)b * TT * HH;

    float g0 = gxp[(size_t)t0 * GG];
    float g1 = gxp[(size_t)(t0 + 1) * GG];
    __syncthreads();

    const int tend = t0 + TCH;
    for (int t = t0; t < tend; ++t) {
        float gxv = g0;
        g0 = g1;
        int tp = t + 2;
        tp = tp < TT ? tp : TT - 1;
        g1 = gxp[(size_t)tp * GG];

        // GEMV: acc = brec[c] + sum_k h[k]*rec[k][c], two independent chains
        unsigned long long acc0 = pk2(brc, 0.0f);
        unsigned long long acc1 = 0ull;
        const ulonglong2* h2 = (const ulonglong2*)h;
#pragma unroll
        for (int j = 0; j < 32; ++j) {
            ulonglong2 hv = h2[j];
            acc0 = ffma2(hv.x, w2[2 * j], acc0);
            acc1 = ffma2(hv.y, w2[2 * j + 1], acc1);
        }
        float a0x, a0y, a1x, a1y;
        upk2(acc0, a0x, a0y);
        upk2(acc1, a1x, a1y);
        float a = (a0x + a1x) + (a0y + a1y);

        if (c < 2 * HH) {
            s[c] = a + gxv;
        } else {
            s[c] = a;
            sgxh[c - 2 * HH] = gxv;
        }
        __syncthreads();

        if (c < HH) {
            float z = sigm(s[c]);
            float r = sigm(s[c + HH]);
            float pre = sgxh[c] + r * s[c + 2 * HH];
            float cand = 2.0f * sigm(2.0f * pre) - 1.0f;  // tanh
            float hn = fmaf(z, hreg - cand, cand);
            hreg = hn;
            h[c] = hn;
            outp[(size_t)t * HH + c] = hn;
        }
        __syncthreads();
    }

    if (c < HH) hstate[b * HH + c] = hreg;
}

// ============================================================================
// fp32 GEMM + bias (+ optional sigmoid), packed f32x2 FMA.
// Operates on a T-chunk: rows (b, t) with t in [t0, t0+TCH).
// blockIdx.x in [0, BB*TCH/64): row base = (blk/4)*TT + t0 + (blk%4)*64.
// ============================================================================
__global__ void __launch_bounds__(256, 2) gemm_bias(
    const float* __restrict__ A, const float* __restrict__ Bm,
    const float* __restrict__ bias, float* __restrict__ C,
    int N, int do_sig, int t0)
{
    extern __shared__ float smem[];
    float* As = smem;            // [64][128]
    float* Bs = smem + 64 * 128; // [128][128]

    const int tid = threadIdx.x;
    const int nb = blockIdx.x;
    const int m0 = (nb >> 2) * TT + t0 + (nb & 3) * 64;
    const int n0 = blockIdx.y * 128;

    const float4* A4 = (const float4*)(A + (size_t)m0 * 128);
    float4* As4 = (float4*)As;
#pragma unroll
    for (int i = 0; i < 8; ++i) {
        int idx = i * 256 + tid;
        As4[idx] = A4[idx];
    }
    const int N4 = N >> 2;
    const float4* B4 = (const float4*)Bm;
    float4* Bs4 = (float4*)Bs;
#pragma unroll
    for (int i = 0; i < 16; ++i) {
        int idx = i * 256 + tid;
        int k = idx >> 5;
        int c4 = idx & 31;
        Bs4[idx] = B4[(size_t)k * N4 + (n0 >> 2) + c4];
    }
    __syncthreads();

    const int rg = tid >> 4;
    const int cg = tid & 15;

    unsigned long long acc[2][4][2];
#pragma unroll
    for (int hf = 0; hf < 2; ++hf)
#pragma unroll
        for (int i = 0; i < 4; ++i) {
            acc[hf][i][0] = 0ull;
            acc[hf][i][1] = 0ull;
        }

    const ulonglong2* BsU = (const ulonglong2*)Bs;

#pragma unroll 8
    for (int k = 0; k < 128; ++k) {
        ulonglong2 bv0 = BsU[k * 32 + cg];
        ulonglong2 bv1 = BsU[k * 32 + 16 + cg];
        float a0 = As[(rg * 4 + 0) * 128 + k];
        float a1 = As[(rg * 4 + 1) * 128 + k];
        float a2 = As[(rg * 4 + 2) * 128 + k];
        float a3 = As[(rg * 4 + 3) * 128 + k];
        unsigned long long aa0 = pk2(a0, a0);
        unsigned long long aa1 = pk2(a1, a1);
        unsigned long long aa2 = pk2(a2, a2);
        unsigned long long aa3 = pk2(a3, a3);

        acc[0][0][0] = ffma2(aa0, bv0.x, acc[0][0][0]);
        acc[0][0][1] = ffma2(aa0, bv0.y, acc[0][0][1]);
        acc[0][1][0] = ffma2(aa1, bv0.x, acc[0][1][0]);
        acc[0][1][1] = ffma2(aa1, bv0.y, acc[0][1][1]);
        acc[0][2][0] = ffma2(aa2, bv0.x, acc[0][2][0]);
        acc[0][2][1] = ffma2(aa2, bv0.y, acc[0][2][1]);
        acc[0][3][0] = ffma2(aa3, bv0.x, acc[0][3][0]);
        acc[0][3][1] = ffma2(aa3, bv0.y, acc[0][3][1]);
        acc[1][0][0] = ffma2(aa0, bv1.x, acc[1][0][0]);
        acc[1][0][1] = ffma2(aa0, bv1.y, acc[1][0][1]);
        acc[1][1][0] = ffma2(aa1, bv1.x, acc[1][1][0]);
        acc[1][1][1] = ffma2(aa1, bv1.y, acc[1][1][1]);
        acc[1][2][0] = ffma2(aa2, bv1.x, acc[1][2][0]);
        acc[1][2][1] = ffma2(aa2, bv1.y, acc[1][2][1]);
        acc[1][3][0] = ffma2(aa3, bv1.x, acc[1][3][0]);
        acc[1][3][1] = ffma2(aa3, bv1.y, acc[1][3][1]);
    }

#pragma unroll
    for (int hf = 0; hf < 2; ++hf) {
        int col = n0 + hf * 64 + cg * 4;
        float4 bb = *(const float4*)(bias + col);
#pragma unroll
        for (int i = 0; i < 4; ++i) {
            float4 v;
            upk2(acc[hf][i][0], v.x, v.y);
            upk2(acc[hf][i][1], v.z, v.w);
            v.x += bb.x; v.y += bb.y; v.z += bb.z; v.w += bb.w;
            if (do_sig) {
                v.x = sigm(v.x); v.y = sigm(v.y);
                v.z = sigm(v.z); v.w = sigm(v.w);
            }
            *(float4*)(C + (size_t)(m0 + rg * 4 + i) * N + col) = v;
        }
    }
}

// ============================================================================
// Streams + events, created once at load (no device memory allocation).
// 6 streams: s[0..2] = scan streams per layer, s[3..5] = gemm streams
// (s[3] also runs the output-projection chunks).
// ============================================================================
struct PipeRes {
    cudaStream_t s[6];
    cudaEvent_t fork;
    cudaEvent_t eg[3][NC];   // gemm(l, i) done
    cudaEvent_t es[3][NC];   // scan(l, i) done
    cudaEvent_t tail[6];
    PipeRes() {
        for (int i = 0; i < 6; ++i)
            cudaStreamCreateWithFlags(&s[i], cudaStreamNonBlocking);
        cudaEventCreateWithFlags(&fork, cudaEventDisableTiming);
        for (int l = 0; l < 3; ++l)
            for (int i = 0; i < NC; ++i) {
                cudaEventCreateWithFlags(&eg[l][i], cudaEventDisableTiming);
                cudaEventCreateWithFlags(&es[l][i], cudaEventDisableTiming);
            }
        for (int i = 0; i < 6; ++i)
            cudaEventCreateWithFlags(&tail[i], cudaEventDisableTiming);
    }
};
static PipeRes P;

extern "C" void kernel_launch(void* const* d_in, const int* in_sizes, int n_in,
                              void* d_out, int out_size)
{
    const float* X    = (const float*)d_in[0];  // [64,2048,128]
    const float* Wk   = (const float*)d_in[1];  // [128,384]
    const float* Wr   = (const float*)d_in[2];  // [128,384]
    const float* bin  = (const float*)d_in[3];  // [384]
    const float* brec = (const float*)d_in[4];  // [384]
    const float* Wo   = (const float*)d_in[5];  // [128,128]
    const float* bo   = (const float*)d_in[6];  // [128]
    float* out = (float*)d_out;                 // [64,2048,128]

    float *gx, *buf, *hst;
    cudaGetSymbolAddress((void**)&gx,  g_gx);
    cudaGetSymbolAddress((void**)&buf, g_buf);
    cudaGetSymbolAddress((void**)&hst, g_h);

    cudaFuncSetAttribute(gemm_bias, cudaFuncAttributeMaxDynamicSharedMemorySize,
                         SMEMG);

    // Fork capture/execution into the 6 worker streams.
    cudaEventRecord(P.fork, 0);
    for (int i = 0; i < 6; ++i) cudaStreamWaitEvent(P.s[i], P.fork, 0);

    const dim3 gg(BB * (TCH / 64), GG / 128);  // 256 x 3
    const dim3 go(BB * (TCH / 64), HH / 128);  // 256 x 1

    for (int l = 0; l < 3; ++l) {
        const float* Ain = (l == 0) ? X : (buf + (size_t)(l - 1) * MTOT * HH);
        float* gxl  = gx  + (size_t)l * MTOT * GG;
        float* bufl = buf + (size_t)l * MTOT * HH;
        float* hl   = hst + (size_t)l * BB * HH;
        cudaStream_t sg = P.s[3 + l];
        cudaStream_t sc = P.s[l];

        for (int i = 0; i < NC; ++i) {
            if (l > 0) cudaStreamWaitEvent(sg, P.es[l - 1][i], 0);
            gemm_bias<<<gg, 256, SMEMG, sg>>>(Ain, Wk, bin, gxl, GG, 0, i * TCH);
            cudaEventRecord(P.eg[l][i], sg);
        }
        for (int i = 0; i < NC; ++i) {
            cudaStreamWaitEvent(sc, P.eg[l][i], 0);
            gru_scan<<<BB, GG, 0, sc>>>(gxl, Wr, brec, bufl, hl, i * TCH);
            cudaEventRecord(P.es[l][i], sc);
        }
    }

    // Output projection + sigmoid, chunked, on s[3] (free after layer-0 gemms).
    for (int i = 0; i < NC; ++i) {
        cudaStreamWaitEvent(P.s[3], P.es[2][i], 0);
        gemm_bias<<<go, 256, SMEMG, P.s[3]>>>(buf + (size_t)2 * MTOT * HH,
                                              Wo, bo, out, HH, 1, i * TCH);
    }

    // Join everything back to the default (capturing) stream.
    for (int i = 0; i < 6; ++i) {
        cudaEventRecord(P.tail[i], P.s[i]);
        cudaStreamWaitEvent(0, P.tail[i], 0);
    }
}

// round 4
// speedup vs baseline: 2.0078x; 1.0644x over previous
#include <cuda_runtime.h>

#define TT 2048
#define BB 64
#define HH 128
#define GG 384
#define MTOT (BB * TT)   // 131072
#define NC 16            // pipeline chunks
#define TCH (TT / NC)    // 128 steps per chunk
#define BPC (TCH / 64)   // gemm blocks per row-chunk
#define SMEMG ((64 * 128 + 128 * 128) * 4)

// Scratch (device globals: no runtime allocation allowed)
__device__ float g_gx[(size_t)3 * MTOT * GG];   // per-layer pre-activations
__device__ float g_buf[(size_t)3 * MTOT * HH];  // per-layer outputs
__device__ float g_h[3 * BB * HH];              // chunk-boundary hidden state

// ---------- packed f32x2 helpers (sm_100+ PTX) ----------
__device__ __forceinline__ unsigned long long pk2(float x, float y) {
    unsigned long long r;
    asm("mov.b64 %0, {%1, %2};" : "=l"(r) : "f"(x), "f"(y));
    return r;
}
__device__ __forceinline__ void upk2(unsigned long long v, float& x, float& y) {
    asm("mov.b64 {%0, %1}, %2;" : "=f"(x), "=f"(y) : "l"(v));
}
__device__ __forceinline__ unsigned long long ffma2(unsigned long long a,
                                                    unsigned long long b,
                                                    unsigned long long c) {
    unsigned long long d;
    asm("fma.rn.f32x2 %0, %1, %2, %3;" : "=l"(d) : "l"(a), "l"(b), "l"(c));
    return d;
}
__device__ __forceinline__ float sigm(float x) {
    return 1.0f / (1.0f + __expf(-x));
}

// ============================================================================
// Chunked persistent GRU scan: one CTA per batch row, steps [t0, t0+TCH).
// gx staged through shared in 4-step groups via coalesced float4 loads
// (12 L1tex wavefronts/step instead of 384 with the naive strided LDG).
// ============================================================================
__global__ void __launch_bounds__(GG, 1) gru_scan(
    const float* __restrict__ gx,    // [B, T, 384]
    const float* __restrict__ rec,   // [128, 384]
    const float* __restrict__ brec,  // [384]
    float* __restrict__ out,         // [B, T, 128]
    float* __restrict__ hstate,      // [B, 128]
    int t0)
{
    __shared__ __align__(16) float h[HH];
    __shared__ float s[GG];
    __shared__ __align__(16) float sbuf[2][4 * GG];  // 2 x 4-step gx stage

    const int b = blockIdx.x;
    const int c = threadIdx.x;  // gate column 0..383

    unsigned long long w2[64];
#pragma unroll
    for (int p = 0; p < 64; ++p)
        w2[p] = pk2(rec[(2 * p) * GG + c], rec[(2 * p + 1) * GG + c]);
    const float brc = brec[c];

    float hreg = 0.0f;
    if (c < HH) {
        hreg = (t0 == 0) ? 0.0f : hstate[b * HH + c];
        h[c] = hreg;
    }

    // Coalesced stage of group 0 (4 steps x 384 floats = 384 float4s).
    const float4* gx4b = (const float4*)(gx + (size_t)b * TT * GG);
    ((float4*)sbuf[0])[c] = gx4b[(size_t)t0 * 96 + c];
    float* outp = out + (size_t)b * TT * HH;
    __syncthreads();

    const int tend = t0 + TCH;
    int cur = 0;
    for (int tg = t0; tg < tend; tg += 4) {
        float4 pf;
        const bool havepf = (tg + 4) < tend;
        if (havepf) pf = gx4b[(size_t)(tg + 4) * 96 + c];

#pragma unroll
        for (int k = 0; k < 4; ++k) {
            // GEMV: acc = brec[c] + sum_k h[k]*rec[k][c], 2 indep chains
            unsigned long long acc0 = pk2(brc, 0.0f);
            unsigned long long acc1 = 0ull;
            const ulonglong2* h2 = (const ulonglong2*)h;
#pragma unroll
            for (int j = 0; j < 32; ++j) {
                ulonglong2 hv = h2[j];
                acc0 = ffma2(hv.x, w2[2 * j], acc0);
                acc1 = ffma2(hv.y, w2[2 * j + 1], acc1);
            }
            float a0x, a0y, a1x, a1y;
            upk2(acc0, a0x, a0y);
            upk2(acc1, a1x, a1y);
            float a = (a0x + a1x) + (a0y + a1y);

            float sv = a;
            if (c < 2 * HH) sv = a + sbuf[cur][k * GG + c];  // z,r: fold x-part
            s[c] = sv;
            __syncthreads();

            if (c < HH) {
                float z = sigm(s[c]);
                float r = sigm(s[c + HH]);
                float gxh = sbuf[cur][k * GG + 2 * HH + c];
                float pre = gxh + r * s[c + 2 * HH];
                float cand = 2.0f * sigm(2.0f * pre) - 1.0f;  // tanh
                float hn = fmaf(z, hreg - cand, cand);
                hreg = hn;
                h[c] = hn;
                outp[(size_t)(tg + k) * HH + c] = hn;
            }
            if (k == 3 && havepf) ((float4*)sbuf[cur ^ 1])[c] = pf;
            __syncthreads();
        }
        cur ^= 1;
    }

    if (c < HH) hstate[b * HH + c] = hreg;
}

// ============================================================================
// fp32 GEMM + bias (+ optional sigmoid), packed f32x2 FMA.
// Operates on a T-chunk: rows (b, t) with t in [t0, t0+TCH).
// ============================================================================
__global__ void __launch_bounds__(256, 2) gemm_bias(
    const float* __restrict__ A, const float* __restrict__ Bm,
    const float* __restrict__ bias, float* __restrict__ C,
    int N, int do_sig, int t0)
{
    extern __shared__ float smem[];
    float* As = smem;            // [64][128]
    float* Bs = smem + 64 * 128; // [128][128]

    const int tid = threadIdx.x;
    const int nb = blockIdx.x;
    const int m0 = (nb / BPC) * TT + t0 + (nb % BPC) * 64;
    const int n0 = blockIdx.y * 128;

    const float4* A4 = (const float4*)(A + (size_t)m0 * 128);
    float4* As4 = (float4*)As;
#pragma unroll
    for (int i = 0; i < 8; ++i) {
        int idx = i * 256 + tid;
        As4[idx] = A4[idx];
    }
    const int N4 = N >> 2;
    const float4* B4 = (const float4*)Bm;
    float4* Bs4 = (float4*)Bs;
#pragma unroll
    for (int i = 0; i < 16; ++i) {
        int idx = i * 256 + tid;
        int k = idx >> 5;
        int c4 = idx & 31;
        Bs4[idx] = B4[(size_t)k * N4 + (n0 >> 2) + c4];
    }
    __syncthreads();

    const int rg = tid >> 4;
    const int cg = tid & 15;

    unsigned long long acc[2][4][2];
#pragma unroll
    for (int hf = 0; hf < 2; ++hf)
#pragma unroll
        for (int i = 0; i < 4; ++i) {
            acc[hf][i][0] = 0ull;
            acc[hf][i][1] = 0ull;
        }

    const ulonglong2* BsU = (const ulonglong2*)Bs;

#pragma unroll 8
    for (int k = 0; k < 128; ++k) {
        ulonglong2 bv0 = BsU[k * 32 + cg];
        ulonglong2 bv1 = BsU[k * 32 + 16 + cg];
        float a0 = As[(rg * 4 + 0) * 128 + k];
        float a1 = As[(rg * 4 + 1) * 128 + k];
        float a2 = As[(rg * 4 + 2) * 128 + k];
        float a3 = As[(rg * 4 + 3) * 128 + k];
        unsigned long long aa0 = pk2(a0, a0);
        unsigned long long aa1 = pk2(a1, a1);
        unsigned long long aa2 = pk2(a2, a2);
        unsigned long long aa3 = pk2(a3, a3);

        acc[0][0][0] = ffma2(aa0, bv0.x, acc[0][0][0]);
        acc[0][0][1] = ffma2(aa0, bv0.y, acc[0][0][1]);
        acc[0][1][0] = ffma2(aa1, bv0.x, acc[0][1][0]);
        acc[0][1][1] = ffma2(aa1, bv0.y, acc[0][1][1]);
        acc[0][2][0] = ffma2(aa2, bv0.x, acc[0][2][0]);
        acc[0][2][1] = ffma2(aa2, bv0.y, acc[0][2][1]);
        acc[0][3][0] = ffma2(aa3, bv0.x, acc[0][3][0]);
        acc[0][3][1] = ffma2(aa3, bv0.y, acc[0][3][1]);
        acc[1][0][0] = ffma2(aa0, bv1.x, acc[1][0][0]);
        acc[1][0][1] = ffma2(aa0, bv1.y, acc[1][0][1]);
        acc[1][1][0] = ffma2(aa1, bv1.x, acc[1][1][0]);
        acc[1][1][1] = ffma2(aa1, bv1.y, acc[1][1][1]);
        acc[1][2][0] = ffma2(aa2, bv1.x, acc[1][2][0]);
        acc[1][2][1] = ffma2(aa2, bv1.y, acc[1][2][1]);
        acc[1][3][0] = ffma2(aa3, bv1.x, acc[1][3][0]);
        acc[1][3][1] = ffma2(aa3, bv1.y, acc[1][3][1]);
    }

#pragma unroll
    for (int hf = 0; hf < 2; ++hf) {
        int col = n0 + hf * 64 + cg * 4;
        float4 bb = *(const float4*)(bias + col);
#pragma unroll
        for (int i = 0; i < 4; ++i) {
            float4 v;
            upk2(acc[hf][i][0], v.x, v.y);
            upk2(acc[hf][i][1], v.z, v.w);
            v.x += bb.x; v.y += bb.y; v.z += bb.z; v.w += bb.w;
            if (do_sig) {
                v.x = sigm(v.x); v.y = sigm(v.y);
                v.z = sigm(v.z); v.w = sigm(v.w);
            }
            *(float4*)(C + (size_t)(m0 + rg * 4 + i) * N + col) = v;
        }
    }
}

// ============================================================================
// Streams + events, created once at load (no device memory allocation).
// ============================================================================
struct PipeRes {
    cudaStream_t s[6];
    cudaEvent_t fork;
    cudaEvent_t eg[3][NC];   // gemm(l, i) done
    cudaEvent_t es[3][NC];   // scan(l, i) done
    cudaEvent_t tail[6];
    PipeRes() {
        for (int i = 0; i < 6; ++i)
            cudaStreamCreateWithFlags(&s[i], cudaStreamNonBlocking);
        cudaEventCreateWithFlags(&fork, cudaEventDisableTiming);
        for (int l = 0; l < 3; ++l)
            for (int i = 0; i < NC; ++i) {
                cudaEventCreateWithFlags(&eg[l][i], cudaEventDisableTiming);
                cudaEventCreateWithFlags(&es[l][i], cudaEventDisableTiming);
            }
        for (int i = 0; i < 6; ++i)
            cudaEventCreateWithFlags(&tail[i], cudaEventDisableTiming);
    }
};
static PipeRes P;

extern "C" void kernel_launch(void* const* d_in, const int* in_sizes, int n_in,
                              void* d_out, int out_size)
{
    const float* X    = (const float*)d_in[0];  // [64,2048,128]
    const float* Wk   = (const float*)d_in[1];  // [128,384]
    const float* Wr   = (const float*)d_in[2];  // [128,384]
    const float* bin  = (const float*)d_in[3];  // [384]
    const float* brec = (const float*)d_in[4];  // [384]
    const float* Wo   = (const float*)d_in[5];  // [128,128]
    const float* bo   = (const float*)d_in[6];  // [128]
    float* out = (float*)d_out;                 // [64,2048,128]

    float *gx, *buf, *hst;
    cudaGetSymbolAddress((void**)&gx,  g_gx);
    cudaGetSymbolAddress((void**)&buf, g_buf);
    cudaGetSymbolAddress((void**)&hst, g_h);

    cudaFuncSetAttribute(gemm_bias, cudaFuncAttributeMaxDynamicSharedMemorySize,
                         SMEMG);

    // Fork capture/execution into the 6 worker streams.
    cudaEventRecord(P.fork, 0);
    for (int i = 0; i < 6; ++i) cudaStreamWaitEvent(P.s[i], P.fork, 0);

    const dim3 gg(BB * BPC, GG / 128);  // 128 x 3
    const dim3 go(BB * BPC, HH / 128);  // 128 x 1

    for (int l = 0; l < 3; ++l) {
        const float* Ain = (l == 0) ? X : (buf + (size_t)(l - 1) * MTOT * HH);
        float* gxl  = gx  + (size_t)l * MTOT * GG;
        float* bufl = buf + (size_t)l * MTOT * HH;
        float* hl   = hst + (size_t)l * BB * HH;
        cudaStream_t sg = P.s[3 + l];
        cudaStream_t sc = P.s[l];

        for (int i = 0; i < NC; ++i) {
            if (l > 0) cudaStreamWaitEvent(sg, P.es[l - 1][i], 0);
            gemm_bias<<<gg, 256, SMEMG, sg>>>(Ain, Wk, bin, gxl, GG, 0, i * TCH);
            cudaEventRecord(P.eg[l][i], sg);
        }
        for (int i = 0; i < NC; ++i) {
            cudaStreamWaitEvent(sc, P.eg[l][i], 0);
            gru_scan<<<BB, GG, 0, sc>>>(gxl, Wr, brec, bufl, hl, i * TCH);
            cudaEventRecord(P.es[l][i], sc);
        }
    }

    // Output projection + sigmoid, chunked, on s[3] (free after layer-0 gemms).
    for (int i = 0; i < NC; ++i) {
        cudaStreamWaitEvent(P.s[3], P.es[2][i], 0);
        gemm_bias<<<go, 256, SMEMG, P.s[3]>>>(buf + (size_t)2 * MTOT * HH,
                                              Wo, bo, out, HH, 1, i * TCH);
    }

    // Join everything back to the default (capturing) stream.
    for (int i = 0; i < 6; ++i) {
        cudaEventRecord(P.tail[i], P.s[i]);
        cudaStreamWaitEvent(0, P.tail[i], 0);
    }
}

// round 5
// speedup vs baseline: 2.0591x; 1.0256x over previous
#include <cuda_runtime.h>

#define TT 2048
#define BB 64
#define HH 128
#define GG 384
#define MTOT (BB * TT)   // 131072
#define NC 32            // pipeline chunks
#define TCH (TT / NC)    // 64 steps per chunk
#define SMEMG ((64 * 128 + 128 * 128) * 4)

// Scratch (device globals: no runtime allocation allowed)
__device__ float g_gx[(size_t)3 * MTOT * GG];   // per-layer pre-activations
__device__ float g_buf[(size_t)3 * MTOT * HH];  // per-layer outputs
__device__ float g_h[3 * BB * HH];              // chunk-boundary hidden state

// ---------- packed f32x2 helpers (sm_100+ PTX) ----------
__device__ __forceinline__ unsigned long long pk2(float x, float y) {
    unsigned long long r;
    asm("mov.b64 %0, {%1, %2};" : "=l"(r) : "f"(x), "f"(y));
    return r;
}
__device__ __forceinline__ void upk2(unsigned long long v, float& x, float& y) {
    asm("mov.b64 {%0, %1}, %2;" : "=f"(x), "=f"(y) : "l"(v));
}
__device__ __forceinline__ unsigned long long ffma2(unsigned long long a,
                                                    unsigned long long b,
                                                    unsigned long long c) {
    unsigned long long d;
    asm("fma.rn.f32x2 %0, %1, %2, %3;" : "=l"(d) : "l"(a), "l"(b), "l"(c));
    return d;
}
__device__ __forceinline__ float sigm(float x) {
    return 1.0f / (1.0f + __expf(-x));
}

// ============================================================================
// Chunked persistent GRU scan, steps [t0, t0+TCH), one CTA per batch row.
//  - thread c<128: z-gate col; 128<=c<256: r-gate col; c>=256: h-gate col.
//  - z/r threads apply sigmoid PRE-barrier (parallel across 8 warps) and STS.
//  - h-threads do the combine: they hold a_h, gx_h and h_old in registers,
//    so post-barrier path is 2 LDS + fma + tanh + 2 fma + STS.
// ============================================================================
__global__ void __launch_bounds__(GG, 1) gru_scan(
    const float* __restrict__ gx,    // [B, T, 384]
    const float* __restrict__ rec,   // [128, 384]
    const float* __restrict__ brec,  // [384]
    float* __restrict__ out,         // [B, T, 128]
    float* __restrict__ hstate,      // [B, 128]
    int t0)
{
    __shared__ __align__(16) float h[HH];
    __shared__ float szr[2 * HH];
    __shared__ __align__(16) float sbuf[2][4 * GG];  // 2 x 4-step gx stage

    const int b = blockIdx.x;
    const int c = threadIdx.x;
    const bool is_h = (c >= 2 * HH);

    unsigned long long w2[64];
#pragma unroll
    for (int p = 0; p < 64; ++p)
        w2[p] = pk2(rec[(2 * p) * GG + c], rec[(2 * p + 1) * GG + c]);
    const float brc = brec[c];

    float hreg = 0.0f;
    if (is_h) {
        hreg = (t0 == 0) ? 0.0f : hstate[b * HH + (c - 2 * HH)];
        h[c - 2 * HH] = hreg;
    }

    const float4* gx4b = (const float4*)(gx + (size_t)b * TT * GG);
    ((float4*)sbuf[0])[c] = gx4b[(size_t)t0 * 96 + c];
    float* outp = out + (size_t)b * TT * HH;
    __syncthreads();

    const int tend = t0 + TCH;
    int cur = 0;
    for (int tg = t0; tg < tend; tg += 4) {
        float4 pf;
        const bool havepf = (tg + 4) < tend;
        if (havepf) pf = gx4b[(size_t)(tg + 4) * 96 + c];

#pragma unroll
        for (int k = 0; k < 4; ++k) {
            // GEMV: a = brec[c] + sum_k h[k]*rec[k][c], 4 indep chains
            unsigned long long a0 = pk2(brc, 0.0f);
            unsigned long long a1 = 0ull, a2 = 0ull, a3 = 0ull;
            const ulonglong2* h4 = (const ulonglong2*)h;
#pragma unroll
            for (int j = 0; j < 16; ++j) {
                ulonglong2 p = h4[2 * j];
                ulonglong2 q = h4[2 * j + 1];
                a0 = ffma2(p.x, w2[4 * j + 0], a0);
                a1 = ffma2(p.y, w2[4 * j + 1], a1);
                a2 = ffma2(q.x, w2[4 * j + 2], a2);
                a3 = ffma2(q.y, w2[4 * j + 3], a3);
            }
            float x0, y0, x1, y1, x2, y2, x3, y3;
            upk2(a0, x0, y0); upk2(a1, x1, y1);
            upk2(a2, x2, y2); upk2(a3, x3, y3);
            float a = ((x0 + x1) + (x2 + x3)) + ((y0 + y1) + (y2 + y3));

            const float gxv = sbuf[cur][k * GG + c];
            if (!is_h) szr[c] = sigm(a + gxv);   // z and r, pre-barrier
            __syncthreads();

            if (is_h) {
                const int cc = c - 2 * HH;
                float z = szr[cc];
                float r = szr[cc + HH];
                float pre = gxv + r * a;
                float cand = 2.0f * sigm(2.0f * pre) - 1.0f;  // tanh
                float hn = fmaf(z, hreg - cand, cand);
                hreg = hn;
                h[cc] = hn;
                outp[(size_t)(tg + k) * HH + cc] = hn;
            }
            if (k == 3 && havepf) ((float4*)sbuf[cur ^ 1])[c] = pf;
            __syncthreads();
        }
        cur ^= 1;
    }

    if (is_h) hstate[b * HH + (c - 2 * HH)] = hreg;
}

// ============================================================================
// fp32 GEMM + bias (+ optional sigmoid), packed f32x2 FMA.
// Chunked: rows (b, t), t in [t0, t0+TCH).  TCH=64 -> one 64-row block per b.
// ============================================================================
__global__ void __launch_bounds__(256, 2) gemm_bias(
    const float* __restrict__ A, const float* __restrict__ Bm,
    const float* __restrict__ bias, float* __restrict__ C,
    int N, int do_sig, int t0)
{
    extern __shared__ float smem[];
    float* As = smem;            // [64][128]
    float* Bs = smem + 64 * 128; // [128][128]

    const int tid = threadIdx.x;
    const int m0 = blockIdx.x * TT + t0;
    const int n0 = blockIdx.y * 128;

    const float4* A4 = (const float4*)(A + (size_t)m0 * 128);
    float4* As4 = (float4*)As;
#pragma unroll
    for (int i = 0; i < 8; ++i) {
        int idx = i * 256 + tid;
        As4[idx] = A4[idx];
    }
    const int N4 = N >> 2;
    const float4* B4 = (const float4*)Bm;
    float4* Bs4 = (float4*)Bs;
#pragma unroll
    for (int i = 0; i < 16; ++i) {
        int idx = i * 256 + tid;
        int k = idx >> 5;
        int c4 = idx & 31;
        Bs4[idx] = B4[(size_t)k * N4 + (n0 >> 2) + c4];
    }
    __syncthreads();

    const int rg = tid >> 4;
    const int cg = tid & 15;

    unsigned long long acc[2][4][2];
#pragma unroll
    for (int hf = 0; hf < 2; ++hf)
#pragma unroll
        for (int i = 0; i < 4; ++i) {
            acc[hf][i][0] = 0ull;
            acc[hf][i][1] = 0ull;
        }

    const ulonglong2* BsU = (const ulonglong2*)Bs;

#pragma unroll 8
    for (int k = 0; k < 128; ++k) {
        ulonglong2 bv0 = BsU[k * 32 + cg];
        ulonglong2 bv1 = BsU[k * 32 + 16 + cg];
        float a0 = As[(rg * 4 + 0) * 128 + k];
        float a1 = As[(rg * 4 + 1) * 128 + k];
        float a2 = As[(rg * 4 + 2) * 128 + k];
        float a3 = As[(rg * 4 + 3) * 128 + k];
        unsigned long long aa0 = pk2(a0, a0);
        unsigned long long aa1 = pk2(a1, a1);
        unsigned long long aa2 = pk2(a2, a2);
        unsigned long long aa3 = pk2(a3, a3);

        acc[0][0][0] = ffma2(aa0, bv0.x, acc[0][0][0]);
        acc[0][0][1] = ffma2(aa0, bv0.y, acc[0][0][1]);
        acc[0][1][0] = ffma2(aa1, bv0.x, acc[0][1][0]);
        acc[0][1][1] = ffma2(aa1, bv0.y, acc[0][1][1]);
        acc[0][2][0] = ffma2(aa2, bv0.x, acc[0][2][0]);
        acc[0][2][1] = ffma2(aa2, bv0.y, acc[0][2][1]);
        acc[0][3][0] = ffma2(aa3, bv0.x, acc[0][3][0]);
        acc[0][3][1] = ffma2(aa3, bv0.y, acc[0][3][1]);
        acc[1][0][0] = ffma2(aa0, bv1.x, acc[1][0][0]);
        acc[1][0][1] = ffma2(aa0, bv1.y, acc[1][0][1]);
        acc[1][1][0] = ffma2(aa1, bv1.x, acc[1][1][0]);
        acc[1][1][1] = ffma2(aa1, bv1.y, acc[1][1][1]);
        acc[1][2][0] = ffma2(aa2, bv1.x, acc[1][2][0]);
        acc[1][2][1] = ffma2(aa2, bv1.y, acc[1][2][1]);
        acc[1][3][0] = ffma2(aa3, bv1.x, acc[1][3][0]);
        acc[1][3][1] = ffma2(aa3, bv1.y, acc[1][3][1]);
    }

#pragma unroll
    for (int hf = 0; hf < 2; ++hf) {
        int col = n0 + hf * 64 + cg * 4;
        float4 bb = *(const float4*)(bias + col);
#pragma unroll
        for (int i = 0; i < 4; ++i) {
            float4 v;
            upk2(acc[hf][i][0], v.x, v.y);
            upk2(acc[hf][i][1], v.z, v.w);
            v.x += bb.x; v.y += bb.y; v.z += bb.z; v.w += bb.w;
            if (do_sig) {
                v.x = sigm(v.x); v.y = sigm(v.y);
                v.z = sigm(v.z); v.w = sigm(v.w);
            }
            *(float4*)(C + (size_t)(m0 + rg * 4 + i) * N + col) = v;
        }
    }
}

// ============================================================================
// Streams + events (created once at load; host objects only, no device mem).
// s[0..2]=scan (HIGH priority), s[3..5]=per-layer gemm, s[6]=out-projection.
// ============================================================================
struct PipeRes {
    cudaStream_t s[7];
    cudaEvent_t fork;
    cudaEvent_t eg[3][NC];   // gemm(l, i) done
    cudaEvent_t es[3][NC];   // scan(l, i) done
    cudaEvent_t tail[7];
    PipeRes() {
        int lo, hi;
        cudaDeviceGetStreamPriorityRange(&lo, &hi);  // hi = greatest priority
        for (int i = 0; i < 3; ++i)
            cudaStreamCreateWithPriority(&s[i], cudaStreamNonBlocking, hi);
        for (int i = 3; i < 7; ++i)
            cudaStreamCreateWithPriority(&s[i], cudaStreamNonBlocking, lo);
        cudaEventCreateWithFlags(&fork, cudaEventDisableTiming);
        for (int l = 0; l < 3; ++l)
            for (int i = 0; i < NC; ++i) {
                cudaEventCreateWithFlags(&eg[l][i], cudaEventDisableTiming);
                cudaEventCreateWithFlags(&es[l][i], cudaEventDisableTiming);
            }
        for (int i = 0; i < 7; ++i)
            cudaEventCreateWithFlags(&tail[i], cudaEventDisableTiming);
    }
};
static PipeRes P;

extern "C" void kernel_launch(void* const* d_in, const int* in_sizes, int n_in,
                              void* d_out, int out_size)
{
    const float* X    = (const float*)d_in[0];  // [64,2048,128]
    const float* Wk   = (const float*)d_in[1];  // [128,384]
    const float* Wr   = (const float*)d_in[2];  // [128,384]
    const float* bin  = (const float*)d_in[3];  // [384]
    const float* brec = (const float*)d_in[4];  // [384]
    const float* Wo   = (const float*)d_in[5];  // [128,128]
    const float* bo   = (const float*)d_in[6];  // [128]
    float* out = (float*)d_out;                 // [64,2048,128]

    float *gx, *buf, *hst;
    cudaGetSymbolAddress((void**)&gx,  g_gx);
    cudaGetSymbolAddress((void**)&buf, g_buf);
    cudaGetSymbolAddress((void**)&hst, g_h);

    cudaFuncSetAttribute(gemm_bias, cudaFuncAttributeMaxDynamicSharedMemorySize,
                         SMEMG);

    // Fork capture into worker streams.
    cudaEventRecord(P.fork, 0);
    for (int i = 0; i < 7; ++i) cudaStreamWaitEvent(P.s[i], P.fork, 0);

    const dim3 gg(BB, GG / 128);  // 64 x 3
    const dim3 go(BB, HH / 128);  // 64 x 1

    // Interleaved enqueue: chunk-major, layer-minor. Throttle each layer's
    // gemm to a 2-chunk lookahead over its own scan to prevent CTA flood.
    for (int i = 0; i < NC; ++i) {
        for (int l = 0; l < 3; ++l) {
            const float* Ain = (l == 0) ? X : (buf + (size_t)(l - 1) * MTOT * HH);
            float* gxl  = gx  + (size_t)l * MTOT * GG;
            float* bufl = buf + (size_t)l * MTOT * HH;
            float* hl   = hst + (size_t)l * BB * HH;
            cudaStream_t sg = P.s[3 + l];
            cudaStream_t sc = P.s[l];

            if (l > 0) cudaStreamWaitEvent(sg, P.es[l - 1][i], 0);
            if (i >= 2) cudaStreamWaitEvent(sg, P.es[l][i - 2], 0);
            gemm_bias<<<gg, 256, SMEMG, sg>>>(Ain, Wk, bin, gxl, GG, 0, i * TCH);
            cudaEventRecord(P.eg[l][i], sg);

            cudaStreamWaitEvent(sc, P.eg[l][i], 0);
            gru_scan<<<BB, GG, 0, sc>>>(gxl, Wr, brec, bufl, hl, i * TCH);
            cudaEventRecord(P.es[l][i], sc);
        }
        // Output projection + sigmoid for chunk i on its own stream.
        cudaStreamWaitEvent(P.s[6], P.es[2][i], 0);
        gemm_bias<<<go, 256, SMEMG, P.s[6]>>>(buf + (size_t)2 * MTOT * HH,
                                              Wo, bo, out, HH, 1, i * TCH);
    }

    // Join everything back to the default (capturing) stream.
    for (int i = 0; i < 7; ++i) {
        cudaEventRecord(P.tail[i], P.s[i]);
        cudaStreamWaitEvent(0, P.tail[i], 0);
    }
}